// round 2
// baseline (speedup 1.0000x reference)
#include <cuda_runtime.h>
#include <cstdint>

// ---------------------------------------------------------------------------
// BatchTopK: keep the k*batch largest ReLU'd values of x (global), zero rest.
// Strategy: exact threshold selection via histogram on float bit patterns
// (positive IEEE floats order identically to their uint32 bits).
//   K1: histogram of elements >= 2.0 into 8192 bins (bits>>17 - 8192), smem.
//   K2: suffix-scan -> threshold bin B*, count strictly above (c_above).
//       If not enough mass >= 2.0, set fallback flag.
//   K3/K4: guarded full-range fallback histogram + scan (normally no-op).
//   K5: out[i] = x[i] if bin > B*, else 0; boundary-bin elements appended to
//       a candidate buffer (value bits + index).
//   K6: single block refines exact threshold bits within the boundary bin,
//       resolves ties at the exact value by smallest index (= lax.top_k
//       stable tie-break), scatters accepted candidates into out.
// ---------------------------------------------------------------------------

#define NBINS_HI   8192
#define NBINS_FULL 16384
#define CAND_CAP   (1u << 22)
#define TIE_CAP    4096

__device__ unsigned g_hist_hi[NBINS_HI];
__device__ unsigned g_hist_full[NBINS_FULL];
__device__ int      g_B_star;     // threshold bin (full bin space); -1 = accept all positives
__device__ unsigned g_c_above;    // count of elements in bins strictly above B*
__device__ unsigned g_k_total;
__device__ int      g_need_full;
__device__ unsigned g_n_cand;
__device__ unsigned g_cand_bits[CAND_CAP];
__device__ unsigned g_cand_idx[CAND_CAP];

__global__ void k_zero() {
    int i = blockIdx.x * blockDim.x + threadIdx.x;
    int stride = gridDim.x * blockDim.x;
    for (int b = i; b < NBINS_HI;   b += stride) g_hist_hi[b]   = 0u;
    for (int b = i; b < NBINS_FULL; b += stride) g_hist_full[b] = 0u;
    if (i == 0) { g_need_full = 0; g_n_cand = 0u; g_B_star = 0x7fffffff; g_c_above = 0u; }
}

// Histogram of elements >= 2.0f (bin = bits>>17, range [8192, 16384)).
__global__ void k_hist_hi(const float4* __restrict__ x4, int n4) {
    __shared__ unsigned sh[NBINS_HI];
    for (int b = threadIdx.x; b < NBINS_HI; b += blockDim.x) sh[b] = 0u;
    __syncthreads();
    int stride = gridDim.x * blockDim.x;
    for (int i = blockIdx.x * blockDim.x + threadIdx.x; i < n4; i += stride) {
        float4 v = x4[i];
        float vals[4] = {v.x, v.y, v.z, v.w};
#pragma unroll
        for (int j = 0; j < 4; j++) {
            if (vals[j] >= 2.0f) {
                unsigned bin = (__float_as_uint(vals[j]) >> 17) - NBINS_HI;
                atomicAdd(&sh[bin], 1u);
            }
        }
    }
    __syncthreads();
    for (int b = threadIdx.x; b < NBINS_HI; b += blockDim.x) {
        unsigned c = sh[b];
        if (c) atomicAdd(&g_hist_hi[b], c);
    }
}

// Fallback: full-range histogram of all positives (global atomics; only runs
// in the pathological case where count(x>=2) < k_total).
__global__ void k_hist_full(const float4* __restrict__ x4, int n4) {
    if (g_need_full == 0) return;
    int stride = gridDim.x * blockDim.x;
    for (int i = blockIdx.x * blockDim.x + threadIdx.x; i < n4; i += stride) {
        float4 v = x4[i];
        float vals[4] = {v.x, v.y, v.z, v.w};
#pragma unroll
        for (int j = 0; j < 4; j++) {
            if (vals[j] > 0.0f)
                atomicAdd(&g_hist_full[__float_as_uint(vals[j]) >> 17], 1u);
        }
    }
}

// Single-block suffix-scan over a histogram to find the threshold bin.
// mode 0: hi histogram (base bin 8192). mode 1: full fallback (guarded).
__global__ void k_scan(int mode, const int* __restrict__ kptr, int n) {
    if (mode == 1 && g_need_full == 0) return;
    const unsigned* hist = mode ? g_hist_full : g_hist_hi;
    const int nbins = mode ? NBINS_FULL : NBINS_HI;
    const int base  = mode ? 0 : NBINS_HI;

    __shared__ unsigned s[1024];
    __shared__ int s_found;
    __shared__ unsigned sK;
    int t = threadIdx.x;
    if (t == 0) {
        s_found = 0;
        if (mode == 0) {
            unsigned batch = (unsigned)(n >> 16);   // d_sae = 65536 per problem spec
            g_k_total = (unsigned)(*kptr) * batch;
        }
        sK = g_k_total;
    }
    __syncthreads();
    unsigned K = sK;
    const int C = nbins / 1024;

    unsigned a = 0;
    for (int jj = 0; jj < C; jj++) a += hist[t * C + jj];
    s[t] = a;
    __syncthreads();
    // inclusive suffix sum (Hillis-Steele)
    for (int off = 1; off < 1024; off <<= 1) {
        unsigned v = (t + off < 1024) ? s[t + off] : 0u;
        __syncthreads();
        s[t] += v;
        __syncthreads();
    }
    // walk own chunk top-down; exactly one thread hits the crossing
    unsigned running = s[t] - a;   // count in bins above this chunk
    for (int jj = C - 1; jj >= 0; --jj) {
        int b = t * C + jj;
        unsigned h = hist[b];
        if (running < K && running + h >= K) {
            g_B_star = base + b;
            g_c_above = running;
            s_found = 1;
        }
        running += h;
    }
    __syncthreads();
    if (t == 0 && !s_found) {
        if (mode == 0) g_need_full = 1;
        else { g_B_star = -1; g_c_above = s[0]; }   // fewer positives than K: keep all
    }
}

// Output pass: write selected values, zero others, collect boundary candidates.
__global__ void k_out(const float4* __restrict__ x4, float4* __restrict__ o4, int n4) {
    const int B = g_B_star;
    int stride = gridDim.x * blockDim.x;
    for (int i = blockIdx.x * blockDim.x + threadIdx.x; i < n4; i += stride) {
        float4 v = x4[i];
        float vals[4] = {v.x, v.y, v.z, v.w};
        float outs[4];
#pragma unroll
        for (int j = 0; j < 4; j++) {
            float val = vals[j];
            float r = 0.0f;
            if (val > 0.0f) {
                unsigned u = __float_as_uint(val);
                int bin = (int)(u >> 17);
                if (bin > B) {
                    r = val;
                } else if (bin == B) {
                    unsigned p = atomicAdd(&g_n_cand, 1u);
                    if (p < CAND_CAP) {
                        g_cand_bits[p] = u;
                        g_cand_idx[p]  = (unsigned)(4 * i + j);
                    }
                }
            }
            outs[j] = r;
        }
        o4[i] = make_float4(outs[0], outs[1], outs[2], outs[3]);
    }
}

// Single-block: refine exact threshold within the boundary bin; scatter.
__global__ void k_select(float* __restrict__ out) {
    __shared__ unsigned h1[512];
    __shared__ unsigned h2[256];
    __shared__ unsigned tie_idx[TIE_CAP];
    __shared__ unsigned s_tcnt;
    __shared__ int s_s1;
    __shared__ unsigned s_c1;
    __shared__ unsigned s_Tbits;
    __shared__ unsigned s_r;
    __shared__ int s_mode;

    int t = threadIdx.x;
    unsigned nc = min(g_n_cand, CAND_CAP);
    int B = g_B_star;
    unsigned K = g_k_total, ca = g_c_above;

    if (t == 0) {
        if (nc == 0u) s_mode = 2;
        else {
            unsigned m = K - ca;
            s_mode = (m >= nc) ? 1 : 0;
        }
    }
    __syncthreads();
    if (s_mode == 2) return;
    if (s_mode == 1) {   // accept every candidate
        for (unsigned i = t; i < nc; i += blockDim.x)
            out[g_cand_idx[i]] = __uint_as_float(g_cand_bits[i]);
        return;
    }
    unsigned m = K - ca;   // how many to accept from the boundary bin

    // level-1 refinement: bits[16:8]
    for (int i = t; i < 512; i += blockDim.x) h1[i] = 0u;
    __syncthreads();
    for (unsigned i = t; i < nc; i += blockDim.x)
        atomicAdd(&h1[(g_cand_bits[i] >> 8) & 0x1FFu], 1u);
    __syncthreads();
    if (t == 0) {
        unsigned running = 0; int s1 = 0; unsigned c1 = 0;
        for (int j = 511; j >= 0; --j) {
            unsigned h = h1[j];
            if (running < m && running + h >= m) { s1 = j; c1 = running; break; }
            running += h;
        }
        s_s1 = s1; s_c1 = c1;
    }
    __syncthreads();
    int s1 = s_s1; unsigned c1 = s_c1;

    // level-2 refinement: bits[7:0] within sub-bin s1
    for (int i = t; i < 256; i += blockDim.x) h2[i] = 0u;
    __syncthreads();
    for (unsigned i = t; i < nc; i += blockDim.x) {
        unsigned bits = g_cand_bits[i];
        if (((bits >> 8) & 0x1FFu) == (unsigned)s1)
            atomicAdd(&h2[bits & 0xFFu], 1u);
    }
    __syncthreads();
    if (t == 0) {
        unsigned m2 = m - c1;
        unsigned running = 0; int b2 = 0; unsigned c2 = 0;
        for (int j = 255; j >= 0; --j) {
            unsigned h = h2[j];
            if (running < m2 && running + h >= m2) { b2 = j; c2 = running; break; }
            running += h;
        }
        s_Tbits = ((unsigned)B << 17) | ((unsigned)s1 << 8) | (unsigned)b2;
        s_r = m2 - c2;          // ties to accept at the exact threshold value
        s_tcnt = 0u;
    }
    __syncthreads();
    unsigned Tb = s_Tbits, r = s_r;

    // scatter strictly-above candidates; gather ties at exact threshold
    for (unsigned i = t; i < nc; i += blockDim.x) {
        unsigned bits = g_cand_bits[i];
        if (bits > Tb) {
            out[g_cand_idx[i]] = __uint_as_float(bits);
        } else if (bits == Tb) {
            unsigned p = atomicAdd(&s_tcnt, 1u);
            if (p < TIE_CAP) tie_idx[p] = g_cand_idx[i];
        }
    }
    __syncthreads();
    unsigned tcnt = min(s_tcnt, (unsigned)TIE_CAP);
    if (r >= tcnt) {   // accept all ties
        for (unsigned i = t; i < tcnt; i += blockDim.x)
            out[tie_idx[i]] = __uint_as_float(Tb);
        return;
    }
    // need the r smallest indices among ties (lax.top_k stable tie-break)
    for (unsigned i = t; i < TIE_CAP; i += blockDim.x)
        if (i >= tcnt) tie_idx[i] = 0xFFFFFFFFu;
    __syncthreads();
    for (unsigned kk = 2; kk <= TIE_CAP; kk <<= 1) {
        for (unsigned j = kk >> 1; j > 0; j >>= 1) {
            for (unsigned i = t; i < TIE_CAP; i += blockDim.x) {
                unsigned ixj = i ^ j;
                if (ixj > i) {
                    unsigned va = tie_idx[i], vb = tie_idx[ixj];
                    bool asc = ((i & kk) == 0);
                    if ((va > vb) == asc) { tie_idx[i] = vb; tie_idx[ixj] = va; }
                }
            }
            __syncthreads();
        }
    }
    for (unsigned i = t; i < r; i += blockDim.x)
        out[tie_idx[i]] = __uint_as_float(Tb);
}

extern "C" void kernel_launch(void* const* d_in, const int* in_sizes, int n_in,
                              void* d_out, int out_size) {
    const float* x    = (const float*)d_in[0];
    const int*   kptr = (const int*)d_in[1];
    float*       out  = (float*)d_out;
    int n  = in_sizes[0];
    int n4 = n >> 2;   // n = 1024*65536, divisible by 4

    k_zero<<<32, 1024>>>();
    k_hist_hi<<<304, 1024>>>((const float4*)x, n4);
    k_scan<<<1, 1024>>>(0, kptr, n);
    k_hist_full<<<304, 256>>>((const float4*)x, n4);   // guarded fallback (no-op normally)
    k_scan<<<1, 1024>>>(1, kptr, n);
    k_out<<<2048, 1024>>>((const float4*)x, (float4*)out, n4);
    k_select<<<1, 1024>>>(out);
}

// round 3
// speedup vs baseline: 1.0440x; 1.0440x over previous
#include <cuda_runtime.h>
#include <cstdint>

// ---------------------------------------------------------------------------
// BatchTopK via exact threshold selection on float bit patterns.
// Pass 1 (k_main): read x once; write out=0 everywhere; smem histogram of
//   elements >= 2.0 (bins = bits>>17 - 8192); compact all >=2.0 candidates
//   into per-warp slabs (no atomics; overflow -> fallback flag).
// k_scan: suffix-scan histogram -> threshold bin B*, count strictly above.
// k_sel1: walk candidate slabs; scatter bin>B* winners; boundary-bin -> buffer.
// k_sel2: single block refines exact threshold bits in boundary bin, resolves
//   value ties by smallest index (lax.top_k stable tie-break), scatters.
// Guarded fallback (full-range histogram + full output pass) preserves
// correctness for any distribution / slab overflow; no-op on normal data.
// ---------------------------------------------------------------------------

#define NBINS_HI   8192
#define NBINS_FULL 16384
#define SLAB       64
#define NUM_WARPS  65536          // 2048 blocks x 32 warps
#define BND_CAP    (1u << 20)
#define TIE_CAP    4096

__device__ unsigned g_hist_hi[NBINS_HI];
__device__ unsigned g_hist_full[NBINS_FULL];
__device__ int      g_B_star;
__device__ unsigned g_c_above;
__device__ unsigned g_k_total;
__device__ int      g_need_full;
__device__ int      g_overflow;
__device__ unsigned g_nb;
__device__ unsigned g_warp_cnt[NUM_WARPS];
__device__ uint2    g_cand[(size_t)NUM_WARPS * SLAB];   // (bits, idx)
__device__ unsigned g_bnd_bits[BND_CAP];
__device__ unsigned g_bnd_idx[BND_CAP];

__global__ void k_zero() {
    int i = blockIdx.x * blockDim.x + threadIdx.x;
    int stride = gridDim.x * blockDim.x;
    for (int b = i; b < NBINS_HI;   b += stride) g_hist_hi[b]   = 0u;
    for (int b = i; b < NBINS_FULL; b += stride) g_hist_full[b] = 0u;
    if (i == 0) {
        g_need_full = 0; g_overflow = 0; g_nb = 0u;
        g_B_star = 0x7fffffff; g_c_above = 0u;
    }
}

// Fused: zero output, histogram (>=2.0), per-warp candidate compaction.
__global__ void __launch_bounds__(1024, 2)
k_main(const float4* __restrict__ x4, float4* __restrict__ o4, int n4) {
    __shared__ unsigned sh[NBINS_HI];
    for (int b = threadIdx.x; b < NBINS_HI; b += blockDim.x) sh[b] = 0u;
    __syncthreads();

    const int lane = threadIdx.x & 31;
    const int W = (blockIdx.x * blockDim.x + threadIdx.x) >> 5;   // global warp id
    const int base4 = W * (SLAB * 4);                             // 256 float4 per warp
    uint2* slab = g_cand + (size_t)W * SLAB;
    unsigned cnt = 0;
    const float4 zero4 = make_float4(0.f, 0.f, 0.f, 0.f);

#pragma unroll
    for (int it = 0; it < 8; it++) {
        int i4 = base4 + it * 32 + lane;
        if (i4 >= n4) break;
        float4 v = x4[i4];
        o4[i4] = zero4;
        float vals[4] = {v.x, v.y, v.z, v.w};
#pragma unroll
        for (int j = 0; j < 4; j++) {
            bool pred = (vals[j] >= 2.0f);
            unsigned u = __float_as_uint(vals[j]);
            if (pred) atomicAdd(&sh[(u >> 17) - NBINS_HI], 1u);
            unsigned mask = __ballot_sync(0xFFFFFFFFu, pred);
            if (pred) {
                unsigned rank = __popc(mask & ((1u << lane) - 1u));
                unsigned pos = cnt + rank;
                if (pos < SLAB) slab[pos] = make_uint2(u, (unsigned)(4 * i4 + j));
                else            g_overflow = 1;
            }
            cnt += __popc(mask);
        }
    }
    if (lane == 0 && W < NUM_WARPS) g_warp_cnt[W] = min(cnt, (unsigned)SLAB);

    __syncthreads();
    for (int b = threadIdx.x; b < NBINS_HI; b += blockDim.x) {
        unsigned c = sh[b];
        if (c) atomicAdd(&g_hist_hi[b], c);
    }
}

// Fallback: full-range histogram of all positives (rare path, guarded).
__global__ void k_hist_full(const float4* __restrict__ x4, int n4) {
    if (g_need_full == 0) return;
    int stride = gridDim.x * blockDim.x;
    for (int i = blockIdx.x * blockDim.x + threadIdx.x; i < n4; i += stride) {
        float4 v = x4[i];
        float vals[4] = {v.x, v.y, v.z, v.w};
#pragma unroll
        for (int j = 0; j < 4; j++)
            if (vals[j] > 0.0f)
                atomicAdd(&g_hist_full[__float_as_uint(vals[j]) >> 17], 1u);
    }
}

// Single-block suffix-scan -> threshold bin. mode 0: hi hist. mode 1: full.
__global__ void k_scan(int mode, const int* __restrict__ kptr, int n) {
    if (mode == 1 && g_need_full == 0) return;
    const unsigned* hist = mode ? g_hist_full : g_hist_hi;
    const int nbins = mode ? NBINS_FULL : NBINS_HI;
    const int base  = mode ? 0 : NBINS_HI;

    __shared__ unsigned s[1024];
    __shared__ int s_found;
    __shared__ unsigned sK;
    int t = threadIdx.x;
    if (t == 0) {
        s_found = 0;
        if (mode == 0) {
            unsigned batch = (unsigned)(n >> 16);   // d_sae = 65536
            g_k_total = (unsigned)(*kptr) * batch;
        }
        sK = g_k_total;
    }
    __syncthreads();
    unsigned K = sK;
    const int C = nbins / 1024;

    unsigned a = 0;
    for (int jj = 0; jj < C; jj++) a += hist[t * C + jj];
    s[t] = a;
    __syncthreads();
    for (int off = 1; off < 1024; off <<= 1) {
        unsigned v = (t + off < 1024) ? s[t + off] : 0u;
        __syncthreads();
        s[t] += v;
        __syncthreads();
    }
    unsigned running = s[t] - a;
    for (int jj = C - 1; jj >= 0; --jj) {
        int b = t * C + jj;
        unsigned h = hist[b];
        if (running < K && running + h >= K) {
            g_B_star = base + b;
            g_c_above = running;
            s_found = 1;
        }
        running += h;
    }
    __syncthreads();
    if (t == 0) {
        if (mode == 0) {
            if (!s_found || g_overflow) g_need_full = 1;
        } else if (!s_found) {
            g_B_star = -1; g_c_above = s[0];   // fewer positives than K: keep all
        }
    }
}

// Walk candidate slabs: scatter winners, collect boundary-bin candidates.
__global__ void k_sel1(float* __restrict__ out) {
    if (g_need_full) return;
    const int B = g_B_star;
    int lane = threadIdx.x & 31;
    int w = (blockIdx.x * blockDim.x + threadIdx.x) >> 5;
    int nw = (gridDim.x * blockDim.x) >> 5;
    for (int s = w; s < NUM_WARPS; s += nw) {
        unsigned cnt = g_warp_cnt[s];
        const uint2* slab = g_cand + (size_t)s * SLAB;
        for (unsigned e = lane; e < cnt; e += 32) {
            uint2 c = slab[e];
            int bin = (int)(c.x >> 17);
            if (bin > B) {
                out[c.y] = __uint_as_float(c.x);
            } else if (bin == B) {
                unsigned p = atomicAdd(&g_nb, 1u);
                if (p < BND_CAP) { g_bnd_bits[p] = c.x; g_bnd_idx[p] = c.y; }
            }
        }
    }
}

// Fallback output pass over full x (guarded; out already zeroed by k_main).
__global__ void k_out_full(const float4* __restrict__ x4, float* __restrict__ out, int n4) {
    if (!g_need_full) return;
    const int B = g_B_star;
    int stride = gridDim.x * blockDim.x;
    for (int i = blockIdx.x * blockDim.x + threadIdx.x; i < n4; i += stride) {
        float4 v = x4[i];
        float vals[4] = {v.x, v.y, v.z, v.w};
#pragma unroll
        for (int j = 0; j < 4; j++) {
            float val = vals[j];
            if (val > 0.0f) {
                unsigned u = __float_as_uint(val);
                int bin = (int)(u >> 17);
                if (bin > B) {
                    out[4 * i + j] = val;
                } else if (bin == B) {
                    unsigned p = atomicAdd(&g_nb, 1u);
                    if (p < BND_CAP) { g_bnd_bits[p] = u; g_bnd_idx[p] = (unsigned)(4 * i + j); }
                }
            }
        }
    }
}

// Single block: refine exact threshold within boundary bin; handle ties.
__global__ void k_sel2(float* __restrict__ out) {
    __shared__ unsigned h1[512];
    __shared__ unsigned h2[256];
    __shared__ unsigned tie_idx[TIE_CAP];
    __shared__ unsigned s_tcnt;
    __shared__ int s_s1;
    __shared__ unsigned s_c1;
    __shared__ unsigned s_Tbits;
    __shared__ unsigned s_r;
    __shared__ int s_mode;

    int t = threadIdx.x;
    unsigned nb = min(g_nb, (unsigned)BND_CAP);
    int B = g_B_star;
    unsigned K = g_k_total, ca = g_c_above;

    if (t == 0) {
        if (nb == 0u || ca >= K) s_mode = 2;
        else {
            unsigned m = K - ca;
            s_mode = (m >= nb) ? 1 : 0;
        }
    }
    __syncthreads();
    if (s_mode == 2) return;
    if (s_mode == 1) {
        for (unsigned i = t; i < nb; i += blockDim.x)
            out[g_bnd_idx[i]] = __uint_as_float(g_bnd_bits[i]);
        return;
    }
    unsigned m = K - ca;

    for (int i = t; i < 512; i += blockDim.x) h1[i] = 0u;
    __syncthreads();
    for (unsigned i = t; i < nb; i += blockDim.x)
        atomicAdd(&h1[(g_bnd_bits[i] >> 8) & 0x1FFu], 1u);
    __syncthreads();
    if (t == 0) {
        unsigned running = 0; int s1 = 0; unsigned c1 = 0;
        for (int j = 511; j >= 0; --j) {
            unsigned h = h1[j];
            if (running < m && running + h >= m) { s1 = j; c1 = running; break; }
            running += h;
        }
        s_s1 = s1; s_c1 = c1;
    }
    __syncthreads();
    int s1 = s_s1; unsigned c1 = s_c1;

    for (int i = t; i < 256; i += blockDim.x) h2[i] = 0u;
    __syncthreads();
    for (unsigned i = t; i < nb; i += blockDim.x) {
        unsigned bits = g_bnd_bits[i];
        if (((bits >> 8) & 0x1FFu) == (unsigned)s1)
            atomicAdd(&h2[bits & 0xFFu], 1u);
    }
    __syncthreads();
    if (t == 0) {
        unsigned m2 = m - c1;
        unsigned running = 0; int b2 = 0; unsigned c2 = 0;
        for (int j = 255; j >= 0; --j) {
            unsigned h = h2[j];
            if (running < m2 && running + h >= m2) { b2 = j; c2 = running; break; }
            running += h;
        }
        s_Tbits = ((unsigned)B << 17) | ((unsigned)s1 << 8) | (unsigned)b2;
        s_r = m2 - c2;
        s_tcnt = 0u;
    }
    __syncthreads();
    unsigned Tb = s_Tbits, r = s_r;

    for (unsigned i = t; i < nb; i += blockDim.x) {
        unsigned bits = g_bnd_bits[i];
        if (bits > Tb) {
            out[g_bnd_idx[i]] = __uint_as_float(bits);
        } else if (bits == Tb) {
            unsigned p = atomicAdd(&s_tcnt, 1u);
            if (p < TIE_CAP) tie_idx[p] = g_bnd_idx[i];
        }
    }
    __syncthreads();
    unsigned tcnt = min(s_tcnt, (unsigned)TIE_CAP);
    if (r >= tcnt) {
        for (unsigned i = t; i < tcnt; i += blockDim.x)
            out[tie_idx[i]] = __uint_as_float(Tb);
        return;
    }
    for (unsigned i = t; i < TIE_CAP; i += blockDim.x)
        if (i >= tcnt) tie_idx[i] = 0xFFFFFFFFu;
    __syncthreads();
    for (unsigned kk = 2; kk <= TIE_CAP; kk <<= 1) {
        for (unsigned j = kk >> 1; j > 0; j >>= 1) {
            for (unsigned i = t; i < TIE_CAP; i += blockDim.x) {
                unsigned ixj = i ^ j;
                if (ixj > i) {
                    unsigned va = tie_idx[i], vb = tie_idx[ixj];
                    bool asc = ((i & kk) == 0);
                    if ((va > vb) == asc) { tie_idx[i] = vb; tie_idx[ixj] = va; }
                }
            }
            __syncthreads();
        }
    }
    for (unsigned i = t; i < r; i += blockDim.x)
        out[tie_idx[i]] = __uint_as_float(Tb);
}

extern "C" void kernel_launch(void* const* d_in, const int* in_sizes, int n_in,
                              void* d_out, int out_size) {
    const float* x    = (const float*)d_in[0];
    const int*   kptr = (const int*)d_in[1];
    float*       out  = (float*)d_out;
    int n  = in_sizes[0];
    int n4 = n >> 2;

    int main_blocks = (n4 + (SLAB * 4 * 32) - 1) / (SLAB * 4 * 32);  // 2048 for 64M

    k_zero<<<32, 1024>>>();
    k_main<<<main_blocks, 1024>>>((const float4*)x, (float4*)out, n4);
    k_scan<<<1, 1024>>>(0, kptr, n);
    k_hist_full<<<304, 256>>>((const float4*)x, n4);     // guarded (no-op normally)
    k_scan<<<1, 1024>>>(1, kptr, n);                     // guarded
    k_sel1<<<128, 1024>>>(out);
    k_out_full<<<304, 1024>>>((const float4*)x, out, n4);// guarded (no-op normally)
    k_sel2<<<1, 1024>>>(out);
}

// round 4
// speedup vs baseline: 1.1579x; 1.1091x over previous
#include <cuda_runtime.h>
#include <cstdint>

// ---------------------------------------------------------------------------
// BatchTopK via exact threshold selection on float bit patterns.
// k_main: fused pass — read x, write out=0, smem histogram of x>=2.0
//   (bins = bits>>17 - 8192, exactly 8192 bins), compact candidates into
//   per-warp slabs using a per-warp smem counter (no ballots).
//   Fast path uses FMNMX max-tree detection (~8 instr/float4).
// k_scan: suffix-scan -> threshold bin B*, count strictly above.
// k_sel1: walk slabs; scatter bin>B* winners; boundary-bin -> buffer.
// k_sel2: single block refines exact threshold bits, resolves value ties by
//   smallest index (lax.top_k stable tie-break), scatters.
// Guarded full-range fallback preserves correctness for any distribution.
// ---------------------------------------------------------------------------

#define NBINS_HI   8192
#define NBINS_FULL 16384
#define SLAB       64
#define NUM_WARPS  65536          // 2048 blocks x 32 warps
#define BND_CAP    (1u << 20)
#define TIE_CAP    4096

__device__ unsigned g_hist_hi[NBINS_HI];
__device__ unsigned g_hist_full[NBINS_FULL];
__device__ int      g_B_star;
__device__ unsigned g_c_above;
__device__ unsigned g_k_total;
__device__ int      g_need_full;
__device__ int      g_overflow;
__device__ unsigned g_nb;
__device__ unsigned g_warp_cnt[NUM_WARPS];
__device__ uint2    g_cand[(size_t)NUM_WARPS * SLAB];   // (bits, idx)
__device__ unsigned g_bnd_bits[BND_CAP];
__device__ unsigned g_bnd_idx[BND_CAP];

__global__ void k_zero() {
    int i = blockIdx.x * blockDim.x + threadIdx.x;
    if (i < NBINS_HI)   g_hist_hi[i]   = 0u;
    if (i < NBINS_FULL) g_hist_full[i] = 0u;
    if (i == 0) {
        g_need_full = 0; g_overflow = 0; g_nb = 0u;
        g_B_star = 0x7fffffff; g_c_above = 0u;
    }
}

// Slow path: exact per-float candidate handling (rare: ~2.3% of floats).
__device__ __forceinline__ void handle4(float4 a, int i4, unsigned* sh,
                                        unsigned* wctr, uint2* slab) {
    float vals[4] = {a.x, a.y, a.z, a.w};
#pragma unroll
    for (int j = 0; j < 4; j++) {
        if (vals[j] >= 2.0f) {
            unsigned u = __float_as_uint(vals[j]);
            atomicAdd(&sh[(u >> 17) - NBINS_HI], 1u);
            unsigned pos = atomicAdd(wctr, 1u);
            if (pos < SLAB) slab[pos] = make_uint2(u, (unsigned)(4 * i4 + j));
            else            g_overflow = 1;
        }
    }
}

// Fused: zero output, histogram (>=2.0), per-warp candidate compaction.
__global__ void __launch_bounds__(1024, 1)
k_main(const float4* __restrict__ x4, float4* __restrict__ o4, int n4) {
    __shared__ unsigned sh[NBINS_HI];
    __shared__ unsigned wcnt[32];
    for (int b = threadIdx.x; b < NBINS_HI; b += 1024) sh[b] = 0u;
    if (threadIdx.x < 32) wcnt[threadIdx.x] = 0u;
    __syncthreads();

    const int lane   = threadIdx.x & 31;
    const int wlocal = threadIdx.x >> 5;
    const int W      = blockIdx.x * 32 + wlocal;
    const int base   = W * 256;                 // 256 float4 per warp
    uint2*    slab   = g_cand + (size_t)W * SLAB;
    unsigned* wctr   = &wcnt[wlocal];
    const float4 z4  = make_float4(0.f, 0.f, 0.f, 0.f);

    if (base + 256 <= n4 && W < NUM_WARPS) {
        // fast path: full tile
        float4 v[8];
#pragma unroll
        for (int it = 0; it < 8; it++) v[it] = x4[base + it * 32 + lane];
#pragma unroll
        for (int it = 0; it < 8; it++) o4[base + it * 32 + lane] = z4;
#pragma unroll
        for (int p = 0; p < 4; p++) {
            float4 a = v[2 * p], b = v[2 * p + 1];
            float m0 = fmaxf(a.x, a.y), m1 = fmaxf(a.z, a.w);
            float m2 = fmaxf(b.x, b.y), m3 = fmaxf(b.z, b.w);
            float m  = fmaxf(fmaxf(m0, m1), fmaxf(m2, m3));
            if (m >= 2.0f) {
                handle4(a, base + (2 * p) * 32 + lane, sh, wctr, slab);
                handle4(b, base + (2 * p + 1) * 32 + lane, sh, wctr, slab);
            }
        }
    } else {
        // tail / oversize guard
        for (int it = 0; it < 8; it++) {
            int i4 = base + it * 32 + lane;
            if (i4 < n4) {
                float4 a = x4[i4];
                o4[i4] = z4;
                if (W < NUM_WARPS) handle4(a, i4, sh, wctr, slab);
                else { // shouldn't happen with fixed shapes; stay correct
                    float vals[4] = {a.x, a.y, a.z, a.w};
                    for (int j = 0; j < 4; j++)
                        if (vals[j] >= 2.0f) g_overflow = 1;
                }
            }
        }
    }
    __syncwarp();
    if (lane == 0 && W < NUM_WARPS) g_warp_cnt[W] = min(wcnt[wlocal], (unsigned)SLAB);

    __syncthreads();
    for (int b = threadIdx.x; b < NBINS_HI; b += 1024) {
        unsigned c = sh[b];
        if (c) atomicAdd(&g_hist_hi[b], c);
    }
}

// Fallback: full-range histogram of all positives (rare path, guarded).
__global__ void k_hist_full(const float4* __restrict__ x4, int n4) {
    if (g_need_full == 0) return;
    int stride = gridDim.x * blockDim.x;
    for (int i = blockIdx.x * blockDim.x + threadIdx.x; i < n4; i += stride) {
        float4 v = x4[i];
        float vals[4] = {v.x, v.y, v.z, v.w};
#pragma unroll
        for (int j = 0; j < 4; j++)
            if (vals[j] > 0.0f)
                atomicAdd(&g_hist_full[__float_as_uint(vals[j]) >> 17], 1u);
    }
}

// Single-block suffix-scan -> threshold bin. mode 0: hi hist. mode 1: full.
__global__ void k_scan(int mode, const int* __restrict__ kptr, int n) {
    if (mode == 1 && g_need_full == 0) return;
    const unsigned* hist = mode ? g_hist_full : g_hist_hi;
    const int nbins = mode ? NBINS_FULL : NBINS_HI;
    const int base  = mode ? 0 : NBINS_HI;

    __shared__ unsigned s[1024];
    __shared__ int s_found;
    __shared__ unsigned sK;
    int t = threadIdx.x;
    if (t == 0) {
        s_found = 0;
        if (mode == 0) {
            unsigned batch = (unsigned)(n >> 16);   // d_sae = 65536
            g_k_total = (unsigned)(*kptr) * batch;
        }
        sK = g_k_total;
    }
    __syncthreads();
    unsigned K = sK;
    const int C = nbins / 1024;

    unsigned a = 0;
    for (int jj = 0; jj < C; jj++) a += hist[t * C + jj];
    s[t] = a;
    __syncthreads();
    for (int off = 1; off < 1024; off <<= 1) {
        unsigned v = (t + off < 1024) ? s[t + off] : 0u;
        __syncthreads();
        s[t] += v;
        __syncthreads();
    }
    unsigned running = s[t] - a;
    for (int jj = C - 1; jj >= 0; --jj) {
        int b = t * C + jj;
        unsigned h = hist[b];
        if (running < K && running + h >= K) {
            g_B_star = base + b;
            g_c_above = running;
            s_found = 1;
        }
        running += h;
    }
    __syncthreads();
    if (t == 0) {
        if (mode == 0) {
            if (!s_found || g_overflow) g_need_full = 1;
        } else if (!s_found) {
            g_B_star = -1; g_c_above = s[0];   // fewer positives than K: keep all
        }
    }
}

// Walk candidate slabs: scatter winners, collect boundary-bin candidates.
__global__ void k_sel1(float* __restrict__ out, int nwarps) {
    if (g_need_full) return;
    const int B = g_B_star;
    int lane = threadIdx.x & 31;
    int w = (blockIdx.x * blockDim.x + threadIdx.x) >> 5;
    int nw = (gridDim.x * blockDim.x) >> 5;
    for (int s = w; s < nwarps; s += nw) {
        unsigned cnt = g_warp_cnt[s];
        const uint2* slab = g_cand + (size_t)s * SLAB;
        for (unsigned e = lane; e < cnt; e += 32) {
            uint2 c = slab[e];
            int bin = (int)(c.x >> 17);
            if (bin > B) {
                out[c.y] = __uint_as_float(c.x);
            } else if (bin == B) {
                unsigned p = atomicAdd(&g_nb, 1u);
                if (p < BND_CAP) { g_bnd_bits[p] = c.x; g_bnd_idx[p] = c.y; }
            }
        }
    }
}

// Fallback output pass over full x (guarded; out already zeroed by k_main).
__global__ void k_out_full(const float4* __restrict__ x4, float* __restrict__ out, int n4) {
    if (!g_need_full) return;
    const int B = g_B_star;
    int stride = gridDim.x * blockDim.x;
    for (int i = blockIdx.x * blockDim.x + threadIdx.x; i < n4; i += stride) {
        float4 v = x4[i];
        float vals[4] = {v.x, v.y, v.z, v.w};
#pragma unroll
        for (int j = 0; j < 4; j++) {
            float val = vals[j];
            if (val > 0.0f) {
                unsigned u = __float_as_uint(val);
                int bin = (int)(u >> 17);
                if (bin > B) {
                    out[4 * i + j] = val;
                } else if (bin == B) {
                    unsigned p = atomicAdd(&g_nb, 1u);
                    if (p < BND_CAP) { g_bnd_bits[p] = u; g_bnd_idx[p] = (unsigned)(4 * i + j); }
                }
            }
        }
    }
}

// Single block: refine exact threshold within boundary bin; handle ties.
__global__ void k_sel2(float* __restrict__ out) {
    __shared__ unsigned h1[512];
    __shared__ unsigned h2[256];
    __shared__ unsigned tie_idx[TIE_CAP];
    __shared__ unsigned s_tcnt;
    __shared__ int s_s1;
    __shared__ unsigned s_c1;
    __shared__ unsigned s_Tbits;
    __shared__ unsigned s_r;
    __shared__ int s_mode;

    int t = threadIdx.x;
    unsigned nb = min(g_nb, (unsigned)BND_CAP);
    int B = g_B_star;
    unsigned K = g_k_total, ca = g_c_above;

    if (t == 0) {
        if (nb == 0u || ca >= K) s_mode = 2;
        else {
            unsigned m = K - ca;
            s_mode = (m >= nb) ? 1 : 0;
        }
    }
    __syncthreads();
    if (s_mode == 2) return;
    if (s_mode == 1) {
        for (unsigned i = t; i < nb; i += blockDim.x)
            out[g_bnd_idx[i]] = __uint_as_float(g_bnd_bits[i]);
        return;
    }
    unsigned m = K - ca;

    for (int i = t; i < 512; i += blockDim.x) h1[i] = 0u;
    __syncthreads();
    for (unsigned i = t; i < nb; i += blockDim.x)
        atomicAdd(&h1[(g_bnd_bits[i] >> 8) & 0x1FFu], 1u);
    __syncthreads();
    if (t == 0) {
        unsigned running = 0; int s1 = 0; unsigned c1 = 0;
        for (int j = 511; j >= 0; --j) {
            unsigned h = h1[j];
            if (running < m && running + h >= m) { s1 = j; c1 = running; break; }
            running += h;
        }
        s_s1 = s1; s_c1 = c1;
    }
    __syncthreads();
    int s1 = s_s1; unsigned c1 = s_c1;

    for (int i = t; i < 256; i += blockDim.x) h2[i] = 0u;
    __syncthreads();
    for (unsigned i = t; i < nb; i += blockDim.x) {
        unsigned bits = g_bnd_bits[i];
        if (((bits >> 8) & 0x1FFu) == (unsigned)s1)
            atomicAdd(&h2[bits & 0xFFu], 1u);
    }
    __syncthreads();
    if (t == 0) {
        unsigned m2 = m - c1;
        unsigned running = 0; int b2 = 0; unsigned c2 = 0;
        for (int j = 255; j >= 0; --j) {
            unsigned h = h2[j];
            if (running < m2 && running + h >= m2) { b2 = j; c2 = running; break; }
            running += h;
        }
        s_Tbits = ((unsigned)B << 17) | ((unsigned)s1 << 8) | (unsigned)b2;
        s_r = m2 - c2;
        s_tcnt = 0u;
    }
    __syncthreads();
    unsigned Tb = s_Tbits, r = s_r;

    for (unsigned i = t; i < nb; i += blockDim.x) {
        unsigned bits = g_bnd_bits[i];
        if (bits > Tb) {
            out[g_bnd_idx[i]] = __uint_as_float(bits);
        } else if (bits == Tb) {
            unsigned p = atomicAdd(&s_tcnt, 1u);
            if (p < TIE_CAP) tie_idx[p] = g_bnd_idx[i];
        }
    }
    __syncthreads();
    unsigned tcnt = min(s_tcnt, (unsigned)TIE_CAP);
    if (r >= tcnt) {
        for (unsigned i = t; i < tcnt; i += blockDim.x)
            out[tie_idx[i]] = __uint_as_float(Tb);
        return;
    }
    for (unsigned i = t; i < TIE_CAP; i += blockDim.x)
        if (i >= tcnt) tie_idx[i] = 0xFFFFFFFFu;
    __syncthreads();
    for (unsigned kk = 2; kk <= TIE_CAP; kk <<= 1) {
        for (unsigned j = kk >> 1; j > 0; j >>= 1) {
            for (unsigned i = t; i < TIE_CAP; i += blockDim.x) {
                unsigned ixj = i ^ j;
                if (ixj > i) {
                    unsigned va = tie_idx[i], vb = tie_idx[ixj];
                    bool asc = ((i & kk) == 0);
                    if ((va > vb) == asc) { tie_idx[i] = vb; tie_idx[ixj] = va; }
                }
            }
            __syncthreads();
        }
    }
    for (unsigned i = t; i < r; i += blockDim.x)
        out[tie_idx[i]] = __uint_as_float(Tb);
}

extern "C" void kernel_launch(void* const* d_in, const int* in_sizes, int n_in,
                              void* d_out, int out_size) {
    const float* x    = (const float*)d_in[0];
    const int*   kptr = (const int*)d_in[1];
    float*       out  = (float*)d_out;
    int n  = in_sizes[0];
    int n4 = n >> 2;

    int main_blocks = (n4 + (SLAB * 4 * 32) - 1) / (SLAB * 4 * 32);  // 2048 for 64M
    int nwarps = main_blocks * 32;
    if (nwarps > NUM_WARPS) nwarps = NUM_WARPS;

    k_zero<<<24, 1024>>>();
    k_main<<<main_blocks, 1024>>>((const float4*)x, (float4*)out, n4);
    k_scan<<<1, 1024>>>(0, kptr, n);
    k_hist_full<<<64, 256>>>((const float4*)x, n4);      // guarded (no-op normally)
    k_scan<<<1, 1024>>>(1, kptr, n);                     // guarded
    k_sel1<<<128, 1024>>>(out, nwarps);
    k_out_full<<<64, 1024>>>((const float4*)x, out, n4); // guarded (no-op normally)
    k_sel2<<<1, 1024>>>(out);
}